// round 6
// baseline (speedup 1.0000x reference)
#include <cuda_runtime.h>

#define HWSZ 1444          // 38*38
#define WDIM 38
#define NA   25
#define NB   512
#define NPLANES (NB * NA)  // 12800

// Anchors: base * scale, scales {0.5, 0.75, 1.0, 1.25, 1.5}, matching
// np.concatenate([_BASE * s for s in scales]) in float32.
__constant__ float c_anchors[NA][2] = {
    {1.3221f*0.50f, 1.73145f*0.50f}, {3.19275f*0.50f, 4.00944f*0.50f},
    {5.05587f*0.50f, 8.09892f*0.50f}, {9.47112f*0.50f, 4.84053f*0.50f},
    {11.2364f*0.50f, 10.0071f*0.50f},
    {1.3221f*0.75f, 1.73145f*0.75f}, {3.19275f*0.75f, 4.00944f*0.75f},
    {5.05587f*0.75f, 8.09892f*0.75f}, {9.47112f*0.75f, 4.84053f*0.75f},
    {11.2364f*0.75f, 10.0071f*0.75f},
    {1.3221f*1.00f, 1.73145f*1.00f}, {3.19275f*1.00f, 4.00944f*1.00f},
    {5.05587f*1.00f, 8.09892f*1.00f}, {9.47112f*1.00f, 4.84053f*1.00f},
    {11.2364f*1.00f, 10.0071f*1.00f},
    {1.3221f*1.25f, 1.73145f*1.25f}, {3.19275f*1.25f, 4.00944f*1.25f},
    {5.05587f*1.25f, 8.09892f*1.25f}, {9.47112f*1.25f, 4.84053f*1.25f},
    {11.2364f*1.25f, 10.0071f*1.25f},
    {1.3221f*1.50f, 1.73145f*1.50f}, {3.19275f*1.50f, 4.00944f*1.50f},
    {5.05587f*1.50f, 8.09892f*1.50f}, {9.47112f*1.50f, 4.84053f*1.50f},
    {11.2364f*1.50f, 10.0071f*1.50f}
};

struct BatchInfo {
    float gxm, gxM, gym, gyM;   // gt box edges
    float gw, gh, gwh;          // gt w, h, w*h
    float tx, ty, tw, th;       // target box values at the special cell
    float tconf;                // target conf at the special cell
    int   best, shw;            // best anchor, flat hw index of special cell
};

__device__ BatchInfo g_binfo[NB];
__device__ double    g_partials[NPLANES];

// ---------------------------------------------------------------------------
// Kernel 1: per-batch metadata (512 threads total).
// ---------------------------------------------------------------------------
__global__ void k_batch_meta(const float* __restrict__ pred,
                             const float* __restrict__ target) {
    int b = threadIdx.x;
    if (b >= NB) return;

    float gx = target[b * 4 + 0] * 38.0f;
    float gy = target[b * 4 + 1] * 38.0f;
    float gw = target[b * 4 + 2] * 38.0f;
    float gh = target[b * 4 + 3] * 38.0f;

    // argmax over anchor IoU (boxes centered at origin):
    // inter = min(aw,gw)*min(ah,gh); union = aw*ah + gw*gh - inter
    int best = 0;
    float best_iou = -1.0f;
#pragma unroll
    for (int a = 0; a < NA; a++) {
        float aw = c_anchors[a][0], ah = c_anchors[a][1];
        float inter = fminf(aw, gw) * fminf(ah, gh);
        float uni = aw * ah + gw * gh - inter;
        float iou = inter / uni;
        if (iou > best_iou) { best_iou = iou; best = a; }
    }

    int gi = (int)gx;
    int gj = (int)gy;
    float aw = c_anchors[best][0], ah = c_anchors[best][1];

    // pred box at the special cell (b, best, :, gj, gi)
    long base = ((long)b * 125 + (long)best * 5) * HWSZ + (long)gj * WDIM + gi;
    float p0 = pred[base];
    float p1 = pred[base + HWSZ];
    float p2 = pred[base + 2 * HWSZ];
    float p3 = pred[base + 3 * HWSZ];

    float bx = 1.0f / (1.0f + expf(-p0)) + (float)gi;
    float by = 1.0f / (1.0f + expf(-p1)) + (float)gj;
    float bw = expf(p2) * aw;
    float bh = expf(p3) * ah;

    float mx = fminf(bx - bw * 0.5f, gx - gw * 0.5f);
    float Mx = fmaxf(bx + bw * 0.5f, gx + gw * 0.5f);
    float my = fminf(by - bh * 0.5f, gy - gh * 0.5f);
    float My = fmaxf(by + bh * 0.5f, gy + gh * 0.5f);
    float cw = bw + gw - (Mx - mx);
    float ch = bh + gh - (My - my);
    float inter = (cw > 0.0f && ch > 0.0f) ? cw * ch : 0.0f;
    float tconf = inter / (bw * bh + gw * gh - inter);

    BatchInfo s;
    s.gxm = gx - gw * 0.5f;  s.gxM = gx + gw * 0.5f;
    s.gym = gy - gh * 0.5f;  s.gyM = gy + gh * 0.5f;
    s.gw = gw; s.gh = gh; s.gwh = gw * gh;
    s.tx = gx - (float)gi;
    s.ty = gy - (float)gj;
    s.tw = logf(gw / aw);
    s.th = logf(gh / ah);
    s.tconf = tconf;
    s.best = best;
    s.shw = gj * WDIM + gi;
    g_binfo[b] = s;
}

// ---------------------------------------------------------------------------
// Kernel 2: fused main loss pass. One block per (batch, anchor) plane.
// Layout: pred[((b*125 + a*5 + comp) * 38 + h) * 38 + w]
// Plane of (b,a) starts at blk*5*1444 floats; comps are +k*1444.
// float4 path: 1444 = 4*361; plane stride 5776 B is 16B-aligned.
// ---------------------------------------------------------------------------
__global__ void __launch_bounds__(256)
k_main(const float* __restrict__ pred) {
    int blk = blockIdx.x;
    int b = blk / NA;
    int a = blk - b * NA;

    BatchInfo bi = g_binfo[b];
    float aw = c_anchors[a][0], ah = c_anchors[a][1];
    int shw = (a == bi.best) ? bi.shw : -1;  // special cell only on best anchor

    const float4* p = reinterpret_cast<const float4*>(pred + (size_t)blk * 5 * HWSZ);

    float acc = 0.0f;
    for (int q = threadIdx.x; q < 361; q += 256) {
        float4 vx = p[q];
        float4 vy = p[q + 361];
        float4 vw = p[q + 722];
        float4 vh = p[q + 1083];
        float4 vc = p[q + 1444];

        float ax[4] = {vx.x, vx.y, vx.z, vx.w};
        float ay[4] = {vy.x, vy.y, vy.z, vy.w};
        float aww[4] = {vw.x, vw.y, vw.z, vw.w};
        float ahh[4] = {vh.x, vh.y, vh.z, vh.w};
        float ac[4] = {vc.x, vc.y, vc.z, vc.w};

        int hw0 = q * 4;
#pragma unroll
        for (int j = 0; j < 4; j++) {
            int hw = hw0 + j;
            int h = hw / WDIM;
            int w = hw - h * WDIM;

            float tx = ax[j], ty = ay[j], tw = aww[j], th = ahh[j], tc = ac[j];

            float sx = __fdividef(1.0f, 1.0f + __expf(-tx));
            float sy = __fdividef(1.0f, 1.0f + __expf(-ty));
            float pc = __fdividef(1.0f, 1.0f + __expf(-tc));
            float bw = __expf(tw) * aw;
            float bh = __expf(th) * ah;

            float bx = sx + (float)w;
            float by = sy + (float)h;
            float hbw = 0.5f * bw, hbh = 0.5f * bh;

            float mx = fminf(bx - hbw, bi.gxm);
            float Mx = fmaxf(bx + hbw, bi.gxM);
            float my = fminf(by - hbh, bi.gym);
            float My = fmaxf(by + hbh, bi.gyM);
            float cw = bi.gw + bw - (Mx - mx);
            float ch = bi.gh + bh - (My - my);
            float inter = (cw > 0.0f && ch > 0.0f) ? cw * ch : 0.0f;
            float uni = bw * bh + bi.gwh - inter;

            bool sp = (hw == shw);
            float txt = sp ? bi.tx : 0.5f;
            float tyt = sp ? bi.ty : 0.5f;
            float twt = sp ? bi.tw : 0.0f;
            float tht = sp ? bi.th : 0.0f;
            float tct = sp ? bi.tconf : 0.0f;
            // conf_mask^2: 5 at special cell, else 0 if iou>0.6 else 1.
            // iou > 0.6  <=>  inter > 0.6*union (union > 0 always).
            float cm2 = sp ? 5.0f : ((inter > 0.6f * uni) ? 0.0f : 1.0f);

            float dx = sx - txt;
            float dy = sy - tyt;
            float dw = tw - twt;
            float dh = th - tht;
            float dc = pc - tct;

            acc += dx * dx + dy * dy + dw * dw + dh * dh + cm2 * (dc * dc);
        }
    }

    // block reduction: warp shuffle (fp32), then 8 warp sums -> double partial
    for (int o = 16; o; o >>= 1) acc += __shfl_xor_sync(0xffffffffu, acc, o);
    __shared__ float warp_s[8];
    int lane = threadIdx.x & 31;
    int wid = threadIdx.x >> 5;
    if (lane == 0) warp_s[wid] = acc;
    __syncthreads();
    if (threadIdx.x == 0) {
        double s = 0.0;
#pragma unroll
        for (int i = 0; i < 8; i++) s += (double)warp_s[i];
        g_partials[blk] = s;
    }
}

// ---------------------------------------------------------------------------
// Kernel 3: final deterministic reduction of 12800 double partials.
// ---------------------------------------------------------------------------
__global__ void k_final(float* __restrict__ out) {
    double s = 0.0;
    for (int i = threadIdx.x; i < NPLANES; i += 1024) s += g_partials[i];
    for (int o = 16; o; o >>= 1) s += __shfl_xor_sync(0xffffffffu, s, o);
    __shared__ double ws[32];
    int lane = threadIdx.x & 31;
    int wid = threadIdx.x >> 5;
    if (lane == 0) ws[wid] = s;
    __syncthreads();
    if (threadIdx.x == 0) {
        double t = 0.0;
#pragma unroll
        for (int i = 0; i < 32; i++) t += ws[i];
        out[0] = (float)(0.5 * t);
    }
}

extern "C" void kernel_launch(void* const* d_in, const int* in_sizes, int n_in,
                              void* d_out, int out_size) {
    const float* pred = (const float*)d_in[0];
    const float* target = (const float*)d_in[1];
    float* out = (float*)d_out;

    k_batch_meta<<<1, NB>>>(pred, target);
    k_main<<<NPLANES, 256>>>(pred);
    k_final<<<1, 1024>>>(out);
}